// round 6
// baseline (speedup 1.0000x reference)
#include <cuda_runtime.h>

// GATEncoder: 2-layer GAT + global mean pool.
// Inputs (metadata order):
//  0: x          [50000,128] f32
//  1: edge_index [2,1600000] i32 OR i64 (JAX x64-dependent; detected at runtime)
//  2: batch      [50000]     i32 OR i64 (sorted)
//  3: W1 [128,64]  4: att_src1 [2,32]  5: att_dst1 [2,32]  6: b1 [64]
//  7: W2 [64,128]  8: att_src2 [1,128] 9: att_dst2 [1,128] 10: b2 [128]
// Output: [64,128] f32

#define NN 50000
#define EE 1600000
#define TE (EE + NN)   // with self loops
#define C1 64
#define C2 128
#define NG 64

// ---- scratch (device globals; no allocation allowed) ----
__device__ __align__(16) float g_xl1[NN * C1];
__device__ __align__(16) float g_as1[NN * 2];
__device__ __align__(16) float g_ad1[NN * 2];
__device__ __align__(16) float g_out1[NN * C1];
__device__ __align__(16) float g_den1[NN * 2];
__device__ __align__(16) float g_h1[NN * C1];
__device__ __align__(16) float g_xl2[NN * C2];
__device__ __align__(16) float g_as2[NN];
__device__ __align__(16) float g_ad2[NN];
__device__ __align__(16) float g_out2[NN * C2];
__device__ __align__(16) float g_den2[NN];
__device__ __align__(16) float g_pool[NG * C2];
__device__ __align__(16) float g_cnt[NG];
__device__ int g_src[TE];
__device__ int g_dst[TE];
__device__ int g_batch[NN];
__device__ unsigned int g_odd_or;   // OR of odd 32-bit words of edge_index

// ============ zero accumulators + flag ============
#define Z_OUT1 (NN * C1 / 4)      // 800000
#define Z_OUT2 (NN * C2 / 4)      // 1600000
#define Z_DEN1 (NN * 2 / 4)       // 25000
#define Z_DEN2 (NN / 4)           // 12500
#define Z_POOL (NG * C2 / 4)      // 2048
#define Z_CNT  (NG / 4)           // 16
#define Z_TOTAL (Z_OUT1 + Z_OUT2 + Z_DEN1 + Z_DEN2 + Z_POOL + Z_CNT)

__global__ void zero_all_kernel() {
    long long i = (long long)blockIdx.x * 256 + threadIdx.x;
    if (i == 0) g_odd_or = 0u;
    float4 z = make_float4(0.f, 0.f, 0.f, 0.f);
    if (i < Z_OUT1) { ((float4*)g_out1)[i] = z; return; }
    i -= Z_OUT1;
    if (i < Z_OUT2) { ((float4*)g_out2)[i] = z; return; }
    i -= Z_OUT2;
    if (i < Z_DEN1) { ((float4*)g_den1)[i] = z; return; }
    i -= Z_DEN1;
    if (i < Z_DEN2) { ((float4*)g_den2)[i] = z; return; }
    i -= Z_DEN2;
    if (i < Z_POOL) { ((float4*)g_pool)[i] = z; return; }
    i -= Z_POOL;
    if (i < Z_CNT)  { ((float4*)g_cnt)[i] = z; }
}

// ============ dtype detection: OR all odd 32-bit words of first 2*EE words ============
// Safe under both dtypes (int32 buffer holds exactly 2*EE words; int64 holds 4*EE).
// If data is int64 (LE, values in [0,50000)), every odd word is 0 -> g_odd_or stays 0.
// If data is int32, odd words are 1.6M random node ids -> g_odd_or != 0 (certain).
__global__ void detect_kernel(const unsigned int* __restrict__ w) {
    unsigned int v = 0;
    long long stride = 2LL * (long long)gridDim.x * blockDim.x;
    for (long long j = 2LL * (blockIdx.x * blockDim.x + threadIdx.x) + 1;
         j < 2LL * EE; j += stride)
        v |= w[j];
#pragma unroll
    for (int o = 16; o; o >>= 1) v |= __shfl_down_sync(0xFFFFFFFFu, v, o);
    if ((threadIdx.x & 31) == 0 && v) atomicOr(&g_odd_or, v);
}

// ============ convert edge_index + batch to int32, append self-loops ============
// Indices clamped to valid range: if dtype detection were ever wrong, we fail
// with a large rel_err (diagnosable, profiled) instead of an illegal access.
__global__ void convert_kernel(const void* __restrict__ ei, const void* __restrict__ batch) {
    int e = blockIdx.x * 256 + threadIdx.x;
    bool is64 = (g_odd_or == 0u);
    if (e < TE) {
        int s, d;
        if (e < EE) {
            if (is64) {
                s = (int)((const long long*)ei)[e];
                d = (int)((const long long*)ei)[EE + e];
            } else {
                s = ((const int*)ei)[e];
                d = ((const int*)ei)[EE + e];
            }
            s = min(max(s, 0), NN - 1);
            d = min(max(d, 0), NN - 1);
        } else { s = d = e - EE; }
        g_src[e] = s; g_dst[e] = d;
    }
    if (e < NN) {
        int g = is64 ? (int)((const long long*)batch)[e] : ((const int*)batch)[e];
        g_batch[e] = min(max(g, 0), NG - 1);
    }
}

// ================= GEMM 1: xl1 = x @ W1  (50000x128 @ 128x64) =================
__global__ void gemm1_kernel(const float* __restrict__ x, const float* __restrict__ W) {
    __shared__ __align__(16) float Ws[128 * 64];
    __shared__ __align__(16) float Xt[128][20];
    int t = threadIdx.x;
    int n0 = blockIdx.x * 16;

    const float4* W4 = (const float4*)W;
    float4* Ws4 = (float4*)Ws;
#pragma unroll
    for (int i = 0; i < 16; i++) Ws4[t + 128 * i] = W4[t + 128 * i];

    {
        int node = t >> 3;
        const float4* xr = (const float4*)(x + (size_t)(n0 + node) * 128);
#pragma unroll
        for (int i = 0; i < 4; i++) {
            int j = (t & 7) + 8 * i;
            float4 v = xr[j];
            int k = 4 * j;
            Xt[k][node] = v.x; Xt[k + 1][node] = v.y;
            Xt[k + 2][node] = v.z; Xt[k + 3][node] = v.w;
        }
    }
    __syncthreads();

    int tc = t & 15;
    int tn = t >> 4;
    float acc[2][4] = {{0.f,0.f,0.f,0.f},{0.f,0.f,0.f,0.f}};
#pragma unroll 8
    for (int k = 0; k < 128; k++) {
        float4 b = *(const float4*)&Ws[k * 64 + 4 * tc];
        float2 a = *(const float2*)&Xt[k][2 * tn];
        acc[0][0] += a.x * b.x; acc[0][1] += a.x * b.y;
        acc[0][2] += a.x * b.z; acc[0][3] += a.x * b.w;
        acc[1][0] += a.y * b.x; acc[1][1] += a.y * b.y;
        acc[1][2] += a.y * b.z; acc[1][3] += a.y * b.w;
    }
#pragma unroll
    for (int i = 0; i < 2; i++) {
        int gn = n0 + 2 * tn + i;
        *(float4*)&g_xl1[(size_t)gn * 64 + 4 * tc] =
            make_float4(acc[i][0], acc[i][1], acc[i][2], acc[i][3]);
    }
}

// ============ attention scores layer 1 ============
__global__ void att1_kernel(const float* __restrict__ att_s, const float* __restrict__ att_d) {
    int n = blockIdx.x;
    int t = threadIdx.x;  // 64
    float v = g_xl1[(size_t)n * 64 + t];
    int h = t >> 5, d = t & 31;
    float s = v * att_s[h * 32 + d];
    float dd = v * att_d[h * 32 + d];
#pragma unroll
    for (int o = 16; o; o >>= 1) {
        s  += __shfl_down_sync(0xFFFFFFFFu, s, o);
        dd += __shfl_down_sync(0xFFFFFFFFu, dd, o);
    }
    if (d == 0) { g_as1[n * 2 + h] = s; g_ad1[n * 2 + h] = dd; }
}

// ================= edge pass layer 1: 16 threads per edge =================
// softmax shift skipped (logits bounded); accumulate Sum(ex*xl[src]) and Sum(ex).
__global__ void edge1_kernel() {
    int gt = blockIdx.x * 256 + threadIdx.x;
    int e = gt >> 4;
    int sub = threadIdx.x & 15;
    int src = 0, dst = 0;
    float ex0 = 0.f, ex1 = 0.f;
    if (sub == 0) {
        src = g_src[e]; dst = g_dst[e];
        float2 as = *(const float2*)&g_as1[2 * src];
        float2 ad = *(const float2*)&g_ad1[2 * dst];
        float e0 = as.x + ad.x; e0 = e0 > 0.f ? e0 : 0.2f * e0;
        float e1 = as.y + ad.y; e1 = e1 > 0.f ? e1 : 0.2f * e1;
        ex0 = __expf(e0); ex1 = __expf(e1);
        atomicAdd(&g_den1[2 * dst],     ex0);
        atomicAdd(&g_den1[2 * dst + 1], ex1);
    }
    src = __shfl_sync(0xFFFFFFFFu, src, 0, 16);
    dst = __shfl_sync(0xFFFFFFFFu, dst, 0, 16);
    ex0 = __shfl_sync(0xFFFFFFFFu, ex0, 0, 16);
    ex1 = __shfl_sync(0xFFFFFFFFu, ex1, 0, 16);
    float exh = (sub < 8) ? ex0 : ex1;
    float4 v = ((const float4*)(g_xl1 + (size_t)src * 64))[sub];
    float4 m = make_float4(v.x * exh, v.y * exh, v.z * exh, v.w * exh);
    atomicAdd(((float4*)(g_out1 + (size_t)dst * 64)) + sub, m);
}

// ============ normalize + bias + ELU (layer 1) -> h1 ============
__global__ void norm1_kernel(const float* __restrict__ b1) {
    int idx = blockIdx.x * 256 + threadIdx.x;
    int c = idx & 63;
    int n = idx >> 6;
    int h = c >> 5;
    float v = g_out1[idx] / g_den1[2 * n + h] + b1[c];
    g_h1[idx] = v > 0.f ? v : (__expf(v) - 1.f);
}

// ================= GEMM 2: xl2 = h1 @ W2  (50000x64 @ 64x128) =================
__global__ void gemm2_kernel(const float* __restrict__ W) {
    __shared__ __align__(16) float Ws[64 * 128];
    __shared__ __align__(16) float Xt[64][36];
    int t = threadIdx.x;  // 256
    int n0 = blockIdx.x * 32;

    const float4* W4 = (const float4*)W;
    float4* Ws4 = (float4*)Ws;
#pragma unroll
    for (int i = 0; i < 8; i++) Ws4[t + 256 * i] = W4[t + 256 * i];

    {
        int node = t >> 3;
        int gn = n0 + node;
        const float4* xr = (const float4*)(g_h1 + (size_t)gn * 64);
#pragma unroll
        for (int i = 0; i < 2; i++) {
            int j = (t & 7) + 8 * i;
            float4 v = (gn < NN) ? xr[j] : make_float4(0.f, 0.f, 0.f, 0.f);
            int k = 4 * j;
            Xt[k][node] = v.x; Xt[k + 1][node] = v.y;
            Xt[k + 2][node] = v.z; Xt[k + 3][node] = v.w;
        }
    }
    __syncthreads();

    int tc = t & 31;
    int tn = t >> 5;
    float acc[4][4];
#pragma unroll
    for (int i = 0; i < 4; i++)
#pragma unroll
        for (int j = 0; j < 4; j++) acc[i][j] = 0.f;

#pragma unroll 8
    for (int k = 0; k < 64; k++) {
        float4 b = *(const float4*)&Ws[k * 128 + 4 * tc];
        float4 a = *(const float4*)&Xt[k][4 * tn];
        acc[0][0] += a.x * b.x; acc[0][1] += a.x * b.y; acc[0][2] += a.x * b.z; acc[0][3] += a.x * b.w;
        acc[1][0] += a.y * b.x; acc[1][1] += a.y * b.y; acc[1][2] += a.y * b.z; acc[1][3] += a.y * b.w;
        acc[2][0] += a.z * b.x; acc[2][1] += a.z * b.y; acc[2][2] += a.z * b.z; acc[2][3] += a.z * b.w;
        acc[3][0] += a.w * b.x; acc[3][1] += a.w * b.y; acc[3][2] += a.w * b.z; acc[3][3] += a.w * b.w;
    }
#pragma unroll
    for (int i = 0; i < 4; i++) {
        int gn = n0 + 4 * tn + i;
        if (gn < NN)
            *(float4*)&g_xl2[(size_t)gn * 128 + 4 * tc] =
                make_float4(acc[i][0], acc[i][1], acc[i][2], acc[i][3]);
    }
}

// ============ attention scores layer 2 ============
__global__ void att2_kernel(const float* __restrict__ att_s, const float* __restrict__ att_d) {
    __shared__ float ss[4], sd[4];
    int n = blockIdx.x;
    int t = threadIdx.x;  // 128
    float v = g_xl2[(size_t)n * 128 + t];
    float s = v * att_s[t];
    float d = v * att_d[t];
#pragma unroll
    for (int o = 16; o; o >>= 1) {
        s += __shfl_down_sync(0xFFFFFFFFu, s, o);
        d += __shfl_down_sync(0xFFFFFFFFu, d, o);
    }
    if ((t & 31) == 0) { ss[t >> 5] = s; sd[t >> 5] = d; }
    __syncthreads();
    if (t == 0) {
        g_as2[n] = ss[0] + ss[1] + ss[2] + ss[3];
        g_ad2[n] = sd[0] + sd[1] + sd[2] + sd[3];
    }
}

// ================= edge pass layer 2: one warp per edge =================
__global__ void edge2_kernel() {
    int gt = blockIdx.x * 256 + threadIdx.x;
    int e = gt >> 5;
    int lane = threadIdx.x & 31;
    int src = 0, dst = 0;
    float ex = 0.f;
    if (lane == 0) {
        src = g_src[e]; dst = g_dst[e];
        float ev = g_as2[src] + g_ad2[dst];
        ev = ev > 0.f ? ev : 0.2f * ev;
        ex = __expf(ev);
        atomicAdd(&g_den2[dst], ex);
    }
    src = __shfl_sync(0xFFFFFFFFu, src, 0);
    dst = __shfl_sync(0xFFFFFFFFu, dst, 0);
    ex  = __shfl_sync(0xFFFFFFFFu, ex, 0);
    float4 v = ((const float4*)(g_xl2 + (size_t)src * 128))[lane];
    float4 m = make_float4(v.x * ex, v.y * ex, v.z * ex, v.w * ex);
    atomicAdd(((float4*)(g_out2 + (size_t)dst * 128)) + lane, m);
}

// ============ normalize + bias + ELU (layer 2) + mean-pool accumulate ============
// batch is sorted: 64 consecutive nodes per block, register-accumulate per graph,
// flush to global atomics only on graph boundary.
__global__ void pool_kernel(const float* __restrict__ b2) {
    int c = threadIdx.x;  // 128
    int n0 = blockIdx.x * 64;
    float acc = 0.f, cnt = 0.f;
    int curg = -1;
    for (int i = 0; i < 64; i++) {
        int n = n0 + i;
        if (n >= NN) break;
        int g = g_batch[n];
        if (g != curg) {
            if (curg >= 0) {
                atomicAdd(&g_pool[curg * 128 + c], acc);
                if (c == 0) atomicAdd(&g_cnt[curg], cnt);
            }
            acc = 0.f; cnt = 0.f; curg = g;
        }
        float v = g_out2[(size_t)n * 128 + c] / g_den2[n] + b2[c];
        v = v > 0.f ? v : (__expf(v) - 1.f);
        acc += v;
        cnt += 1.f;
    }
    if (curg >= 0) {
        atomicAdd(&g_pool[curg * 128 + c], acc);
        if (c == 0) atomicAdd(&g_cnt[curg], cnt);
    }
}

__global__ void final_kernel(float* __restrict__ out) {
    int g = blockIdx.x, c = threadIdx.x;
    out[g * 128 + c] = g_pool[g * 128 + c] / fmaxf(g_cnt[g], 1.f);
}

// ============================ launch ============================
extern "C" void kernel_launch(void* const* d_in, const int* in_sizes, int n_in,
                              void* d_out, int out_size) {
    const float* x   = (const float*)d_in[0];
    const void*  ei  = d_in[1];
    const void*  bat = d_in[2];
    const float* W1  = (const float*)d_in[3];
    const float* as1 = (const float*)d_in[4];
    const float* ad1 = (const float*)d_in[5];
    const float* b1  = (const float*)d_in[6];
    const float* W2  = (const float*)d_in[7];
    const float* as2 = (const float*)d_in[8];
    const float* ad2 = (const float*)d_in[9];
    const float* b2  = (const float*)d_in[10];
    float* out = (float*)d_out;

    zero_all_kernel<<<(Z_TOTAL + 255) / 256, 256>>>();
    detect_kernel<<<512, 256>>>((const unsigned int*)ei);
    convert_kernel<<<(TE + 255) / 256, 256>>>(ei, bat);

    gemm1_kernel<<<NN / 16, 128>>>(x, W1);
    att1_kernel<<<NN, 64>>>(as1, ad1);
    edge1_kernel<<<(TE * 16) / 256, 256>>>();            // 103125 blocks, exact
    norm1_kernel<<<(NN * C1) / 256, 256>>>(b1);          // 12500 blocks, exact
    gemm2_kernel<<<(NN + 31) / 32, 256>>>(W2);
    att2_kernel<<<NN, 128>>>(as2, ad2);
    edge2_kernel<<<(TE * 32) / 256, 256>>>();            // 206250 blocks, exact
    pool_kernel<<<(NN + 63) / 64, 128>>>(b2);
    final_kernel<<<NG, 128>>>(out);
}

// round 7
// speedup vs baseline: 1.9840x; 1.9840x over previous
#include <cuda_runtime.h>

// GATEncoder: 2-layer GAT + global mean pool.
// Inputs (metadata order):
//  0: x          [50000,128] f32
//  1: edge_index [2,1600000] i32 OR i64 (JAX x64-dependent; detected at runtime)
//  2: batch      [50000]     i32 OR i64 (sorted)
//  3: W1 [128,64]  4: att_src1 [2,32]  5: att_dst1 [2,32]  6: b1 [64]
//  7: W2 [64,128]  8: att_src2 [1,128] 9: att_dst2 [1,128] 10: b2 [128]
// Output: [64,128] f32

#define NN 50000
#define EE 1600000
#define TE (EE + NN)   // with self loops
#define C1 64
#define C2 128
#define NG 64

// ---- scratch (device globals; no allocation allowed) ----
__device__ __align__(16) float g_xl1[NN * C1];
__device__ __align__(16) float g_as1[NN * 2];
__device__ __align__(16) float g_ad1[NN * 2];
__device__ __align__(16) float g_out1[NN * C1];
__device__ __align__(16) float g_den1[NN * 2];
__device__ __align__(16) float g_xl2[NN * C2];
__device__ __align__(16) float g_as2[NN];
__device__ __align__(16) float g_ad2[NN];
__device__ __align__(16) float g_out2[NN * C2];
__device__ __align__(16) float g_den2[NN];
__device__ __align__(16) float g_pool[NG * C2];
__device__ __align__(16) float g_cnt[NG];
__device__ int g_src[TE];
__device__ int g_dst[TE];
__device__ int g_batch[NN];
__device__ unsigned int g_odd_or;   // OR of odd 32-bit words of edge_index

// ============ zero accumulators + flag ============
#define Z_OUT1 (NN * C1 / 4)
#define Z_OUT2 (NN * C2 / 4)
#define Z_DEN1 (NN * 2 / 4)
#define Z_DEN2 (NN / 4)
#define Z_POOL (NG * C2 / 4)
#define Z_CNT  (NG / 4)
#define Z_TOTAL (Z_OUT1 + Z_OUT2 + Z_DEN1 + Z_DEN2 + Z_POOL + Z_CNT)

__global__ void zero_all_kernel() {
    long long i = (long long)blockIdx.x * 256 + threadIdx.x;
    if (i == 0) g_odd_or = 0u;
    float4 z = make_float4(0.f, 0.f, 0.f, 0.f);
    if (i < Z_OUT1) { ((float4*)g_out1)[i] = z; return; }
    i -= Z_OUT1;
    if (i < Z_OUT2) { ((float4*)g_out2)[i] = z; return; }
    i -= Z_OUT2;
    if (i < Z_DEN1) { ((float4*)g_den1)[i] = z; return; }
    i -= Z_DEN1;
    if (i < Z_DEN2) { ((float4*)g_den2)[i] = z; return; }
    i -= Z_DEN2;
    if (i < Z_POOL) { ((float4*)g_pool)[i] = z; return; }
    i -= Z_POOL;
    if (i < Z_CNT)  { ((float4*)g_cnt)[i] = z; }
}

// ============ dtype detection (odd 32-bit words all zero <=> int64 LE) ============
__global__ void detect_kernel(const unsigned int* __restrict__ w) {
    unsigned int v = 0;
    long long stride = 2LL * (long long)gridDim.x * blockDim.x;
    for (long long j = 2LL * (blockIdx.x * blockDim.x + threadIdx.x) + 1;
         j < 2LL * EE; j += stride)
        v |= w[j];
#pragma unroll
    for (int o = 16; o; o >>= 1) v |= __shfl_down_sync(0xFFFFFFFFu, v, o);
    if ((threadIdx.x & 31) == 0 && v) atomicOr(&g_odd_or, v);
}

// ============ convert edge_index + batch to int32, append self-loops ============
__global__ void convert_kernel(const void* __restrict__ ei, const void* __restrict__ batch) {
    int e = blockIdx.x * 256 + threadIdx.x;
    bool is64 = (g_odd_or == 0u);
    if (e < TE) {
        int s, d;
        if (e < EE) {
            if (is64) {
                s = (int)((const long long*)ei)[e];
                d = (int)((const long long*)ei)[EE + e];
            } else {
                s = ((const int*)ei)[e];
                d = ((const int*)ei)[EE + e];
            }
            s = min(max(s, 0), NN - 1);
            d = min(max(d, 0), NN - 1);
        } else { s = d = e - EE; }
        g_src[e] = s; g_dst[e] = d;
    }
    if (e < NN) {
        int g = is64 ? (int)((const long long*)batch)[e] : ((const int*)batch)[e];
        g_batch[e] = min(max(g, 0), NG - 1);
    }
}

// ================= GEMM 1 + att1 epilogue =================
// Tile: 64 nodes x 64 cols, 256 threads, K chunks of 32, per-thread 4x4.
// Epilogue: per-node dot with att_src1/att_dst1 via width-8 shuffle reduce
// (lanes tc 0-7 = head0 cols, tc 8-15 = head1 cols).
__global__ void gemm1_kernel(const float* __restrict__ x, const float* __restrict__ W,
                             const float* __restrict__ atts, const float* __restrict__ attd) {
    __shared__ __align__(16) float Xs[32][68];   // [k][node]
    __shared__ __align__(16) float Ws[32 * 64];
    int t = threadIdx.x;                 // 256
    int n0 = blockIdx.x * 64;
    int node = t >> 2, q = t & 3;
    int tn = t >> 4, tc = t & 15;
    float acc[4][4] = {};
    const float4* W4 = (const float4*)W;

    for (int k0 = 0; k0 < 128; k0 += 32) {
        // W chunk: rows k0..k0+31 are contiguous (8KB linear copy)
        ((float4*)Ws)[t]       = W4[k0 * 16 + t];
        ((float4*)Ws)[t + 256] = W4[k0 * 16 + t + 256];
        // X chunk, transposed into Xs[k][node]
        int gn = n0 + node;
        const float4* xr = (const float4*)(x + (size_t)gn * 128 + k0);
#pragma unroll
        for (int i = 0; i < 2; i++) {
            int jj = 2 * q + i;          // 0..7 -> k = 8q+4i
            float4 v = (gn < NN) ? xr[jj] : make_float4(0.f, 0.f, 0.f, 0.f);
            int k = 4 * jj;
            Xs[k][node] = v.x; Xs[k + 1][node] = v.y;
            Xs[k + 2][node] = v.z; Xs[k + 3][node] = v.w;
        }
        __syncthreads();
#pragma unroll
        for (int k = 0; k < 32; k++) {
            float4 b = *(const float4*)&Ws[k * 64 + 4 * tc];
            float4 a = *(const float4*)&Xs[k][4 * tn];
            acc[0][0] += a.x * b.x; acc[0][1] += a.x * b.y; acc[0][2] += a.x * b.z; acc[0][3] += a.x * b.w;
            acc[1][0] += a.y * b.x; acc[1][1] += a.y * b.y; acc[1][2] += a.y * b.z; acc[1][3] += a.y * b.w;
            acc[2][0] += a.z * b.x; acc[2][1] += a.z * b.y; acc[2][2] += a.z * b.z; acc[2][3] += a.z * b.w;
            acc[3][0] += a.w * b.x; acc[3][1] += a.w * b.y; acc[3][2] += a.w * b.z; acc[3][3] += a.w * b.w;
        }
        __syncthreads();
    }

    // epilogue: store xl1 + fused attention dots
    float4 asv = *(const float4*)(atts + 4 * tc);   // att_src1 flat [64]
    float4 adv = *(const float4*)(attd + 4 * tc);
#pragma unroll
    for (int i = 0; i < 4; i++) {
        int gn = n0 + 4 * tn + i;
        if (gn < NN)
            *(float4*)&g_xl1[(size_t)gn * 64 + 4 * tc] =
                make_float4(acc[i][0], acc[i][1], acc[i][2], acc[i][3]);
        float s = acc[i][0] * asv.x + acc[i][1] * asv.y + acc[i][2] * asv.z + acc[i][3] * asv.w;
        float d = acc[i][0] * adv.x + acc[i][1] * adv.y + acc[i][2] * adv.z + acc[i][3] * adv.w;
#pragma unroll
        for (int o = 4; o; o >>= 1) {
            s += __shfl_down_sync(0xFFFFFFFFu, s, o, 8);
            d += __shfl_down_sync(0xFFFFFFFFu, d, o, 8);
        }
        if (gn < NN) {
            if (tc == 0) { g_as1[2 * gn]     = s; g_ad1[2 * gn]     = d; }
            if (tc == 8) { g_as1[2 * gn + 1] = s; g_ad1[2 * gn + 1] = d; }
        }
    }
}

// ================= edge pass layer 1: 8 threads/edge, no divergence =================
// All lanes recompute scores (broadcast loads). lane sub handles float4 sub (head0)
// and sub+8 (head1). Softmax shift skipped (logits bounded).
__global__ void edge1_kernel() {
    long long gt = (long long)blockIdx.x * 256 + threadIdx.x;
    int e = (int)(gt >> 3);
    if (e >= TE) return;
    int sub = threadIdx.x & 7;
    int src = g_src[e], dst = g_dst[e];
    float2 as = *(const float2*)&g_as1[2 * src];
    float2 ad = *(const float2*)&g_ad1[2 * dst];
    float e0 = as.x + ad.x; e0 = e0 > 0.f ? e0 : 0.2f * e0;
    float e1 = as.y + ad.y; e1 = e1 > 0.f ? e1 : 0.2f * e1;
    float ex0 = __expf(e0), ex1 = __expf(e1);
    if (sub == 0) atomicAdd(&g_den1[2 * dst],     ex0);
    if (sub == 1) atomicAdd(&g_den1[2 * dst + 1], ex1);
    const float4* vr = (const float4*)(g_xl1 + (size_t)src * 64);
    float4* orow = (float4*)(g_out1 + (size_t)dst * 64);
    float4 v0 = vr[sub];
    atomicAdd(orow + sub, make_float4(v0.x * ex0, v0.y * ex0, v0.z * ex0, v0.w * ex0));
    float4 v1 = vr[sub + 8];
    atomicAdd(orow + sub + 8, make_float4(v1.x * ex1, v1.y * ex1, v1.z * ex1, v1.w * ex1));
}

// ================= GEMM 2 (fused norm1+bias+ELU on input) + att2 epilogue =================
// Tile: 64 nodes x 128 cols, 256 threads, K chunks of 32, per-thread 4x8.
__global__ void gemm2_kernel(const float* __restrict__ W, const float* __restrict__ b1,
                             const float* __restrict__ atts, const float* __restrict__ attd) {
    __shared__ __align__(16) float Xs[32][68];
    __shared__ __align__(16) float Ws[32 * 128];
    int t = threadIdx.x;                 // 256
    int n0 = blockIdx.x * 64;
    int node = t >> 2, q = t & 3;
    int tn = t >> 4, tc = t & 15;
    float acc[4][8] = {};

    for (int k0 = 0; k0 < 64; k0 += 32) {
        // W chunk: rows k0..k0+31 contiguous (16KB linear)
        const float4* W4 = (const float4*)(W + k0 * 128);
#pragma unroll
        for (int i = 0; i < 4; i++)
            ((float4*)Ws)[t + 256 * i] = W4[t + 256 * i];
        // X chunk = elu(out1/den1 + b1), transposed
        int gn = n0 + node;
        float2 dn = (gn < NN) ? *(const float2*)&g_den1[2 * gn] : make_float2(1.f, 1.f);
        const float4* orow = (const float4*)(g_out1 + (size_t)gn * 64 + k0);
#pragma unroll
        for (int i = 0; i < 2; i++) {
            int jj = 2 * q + i;
            int col = k0 + 4 * jj;
            float4 v = (gn < NN) ? orow[jj] : make_float4(0.f, 0.f, 0.f, 0.f);
            float den = (col >= 32) ? dn.y : dn.x;
            float4 bb = *(const float4*)(b1 + col);
            float rd = 1.f / den;
            v.x = v.x * rd + bb.x; v.x = v.x > 0.f ? v.x : (__expf(v.x) - 1.f);
            v.y = v.y * rd + bb.y; v.y = v.y > 0.f ? v.y : (__expf(v.y) - 1.f);
            v.z = v.z * rd + bb.z; v.z = v.z > 0.f ? v.z : (__expf(v.z) - 1.f);
            v.w = v.w * rd + bb.w; v.w = v.w > 0.f ? v.w : (__expf(v.w) - 1.f);
            int k = 4 * jj;
            Xs[k][node] = v.x; Xs[k + 1][node] = v.y;
            Xs[k + 2][node] = v.z; Xs[k + 3][node] = v.w;
        }
        __syncthreads();
#pragma unroll
        for (int k = 0; k < 32; k++) {
            float4 a  = *(const float4*)&Xs[k][4 * tn];
            float4 b0 = *(const float4*)&Ws[k * 128 + 8 * tc];
            float4 b1v = *(const float4*)&Ws[k * 128 + 8 * tc + 4];
#pragma unroll
            for (int i = 0; i < 4; i++) {
                float ai = (i == 0) ? a.x : (i == 1) ? a.y : (i == 2) ? a.z : a.w;
                acc[i][0] += ai * b0.x; acc[i][1] += ai * b0.y;
                acc[i][2] += ai * b0.z; acc[i][3] += ai * b0.w;
                acc[i][4] += ai * b1v.x; acc[i][5] += ai * b1v.y;
                acc[i][6] += ai * b1v.z; acc[i][7] += ai * b1v.w;
            }
        }
        __syncthreads();
    }

    // epilogue: store xl2 + fused single-head attention dots (width-16 reduce)
    float4 as0 = *(const float4*)(atts + 8 * tc), asv1 = *(const float4*)(atts + 8 * tc + 4);
    float4 ad0 = *(const float4*)(attd + 8 * tc), adv1 = *(const float4*)(attd + 8 * tc + 4);
#pragma unroll
    for (int i = 0; i < 4; i++) {
        int gn = n0 + 4 * tn + i;
        if (gn < NN) {
            float4* xr = (float4*)(g_xl2 + (size_t)gn * 128 + 8 * tc);
            xr[0] = make_float4(acc[i][0], acc[i][1], acc[i][2], acc[i][3]);
            xr[1] = make_float4(acc[i][4], acc[i][5], acc[i][6], acc[i][7]);
        }
        float s = acc[i][0] * as0.x + acc[i][1] * as0.y + acc[i][2] * as0.z + acc[i][3] * as0.w
                + acc[i][4] * asv1.x + acc[i][5] * asv1.y + acc[i][6] * asv1.z + acc[i][7] * asv1.w;
        float d = acc[i][0] * ad0.x + acc[i][1] * ad0.y + acc[i][2] * ad0.z + acc[i][3] * ad0.w
                + acc[i][4] * adv1.x + acc[i][5] * adv1.y + acc[i][6] * adv1.z + acc[i][7] * adv1.w;
#pragma unroll
        for (int o = 8; o; o >>= 1) {
            s += __shfl_down_sync(0xFFFFFFFFu, s, o, 16);
            d += __shfl_down_sync(0xFFFFFFFFu, d, o, 16);
        }
        if (gn < NN && tc == 0) { g_as2[gn] = s; g_ad2[gn] = d; }
    }
}

// ================= edge pass layer 2: 16 threads/edge, no divergence =================
__global__ void edge2_kernel() {
    int gt = blockIdx.x * 256 + threadIdx.x;
    int e = gt >> 4;
    int sub = threadIdx.x & 15;
    int src = g_src[e], dst = g_dst[e];
    float ev = g_as2[src] + g_ad2[dst];
    ev = ev > 0.f ? ev : 0.2f * ev;
    float ex = __expf(ev);
    if (sub == 0) atomicAdd(&g_den2[dst], ex);
    const float4* vr = (const float4*)(g_xl2 + (size_t)src * 128);
    float4* orow = (float4*)(g_out2 + (size_t)dst * 128);
    float4 v0 = vr[sub];
    atomicAdd(orow + sub, make_float4(v0.x * ex, v0.y * ex, v0.z * ex, v0.w * ex));
    float4 v1 = vr[sub + 16];
    atomicAdd(orow + sub + 16, make_float4(v1.x * ex, v1.y * ex, v1.z * ex, v1.w * ex));
}

// ============ normalize + bias + ELU (layer 2) + mean-pool accumulate ============
__global__ void pool_kernel(const float* __restrict__ b2) {
    int c = threadIdx.x;  // 128
    int n0 = blockIdx.x * 64;
    float acc = 0.f, cnt = 0.f;
    int curg = -1;
    for (int i = 0; i < 64; i++) {
        int n = n0 + i;
        if (n >= NN) break;
        int g = g_batch[n];
        if (g != curg) {
            if (curg >= 0) {
                atomicAdd(&g_pool[curg * 128 + c], acc);
                if (c == 0) atomicAdd(&g_cnt[curg], cnt);
            }
            acc = 0.f; cnt = 0.f; curg = g;
        }
        float v = g_out2[(size_t)n * 128 + c] / g_den2[n] + b2[c];
        v = v > 0.f ? v : (__expf(v) - 1.f);
        acc += v;
        cnt += 1.f;
    }
    if (curg >= 0) {
        atomicAdd(&g_pool[curg * 128 + c], acc);
        if (c == 0) atomicAdd(&g_cnt[curg], cnt);
    }
}

__global__ void final_kernel(float* __restrict__ out) {
    int g = blockIdx.x, c = threadIdx.x;
    out[g * 128 + c] = g_pool[g * 128 + c] / fmaxf(g_cnt[g], 1.f);
}

// ============================ launch ============================
extern "C" void kernel_launch(void* const* d_in, const int* in_sizes, int n_in,
                              void* d_out, int out_size) {
    const float* x   = (const float*)d_in[0];
    const void*  ei  = d_in[1];
    const void*  bat = d_in[2];
    const float* W1  = (const float*)d_in[3];
    const float* as1 = (const float*)d_in[4];
    const float* ad1 = (const float*)d_in[5];
    const float* b1  = (const float*)d_in[6];
    const float* W2  = (const float*)d_in[7];
    const float* as2 = (const float*)d_in[8];
    const float* ad2 = (const float*)d_in[9];
    const float* b2  = (const float*)d_in[10];
    float* out = (float*)d_out;

    zero_all_kernel<<<(Z_TOTAL + 255) / 256, 256>>>();
    detect_kernel<<<512, 256>>>((const unsigned int*)ei);
    convert_kernel<<<(TE + 255) / 256, 256>>>(ei, bat);

    gemm1_kernel<<<(NN + 63) / 64, 256>>>(x, W1, as1, ad1);               // 782 blocks
    edge1_kernel<<<(int)((8LL * TE + 255) / 256), 256>>>();               // 51563 blocks
    gemm2_kernel<<<(NN + 63) / 64, 256>>>(W2, b1, as2, ad2);              // 782 blocks
    edge2_kernel<<<(TE * 16) / 256, 256>>>();                             // 103125 blocks, exact
    pool_kernel<<<(NN + 63) / 64, 128>>>(b2);
    final_kernel<<<NG, 128>>>(out);
}

// round 8
// speedup vs baseline: 2.8292x; 1.4260x over previous
#include <cuda_runtime.h>

// GATEncoder: 2-layer GAT + global mean pool. CSR gather formulation.
//  0: x [50000,128] f32   1: edge_index [2,1.6M] i32/i64 (detected)   2: batch [50000] (sorted)
//  3: W1 [128,64]  4: att_src1 [2,32]  5: att_dst1 [2,32]  6: b1 [64]
//  7: W2 [64,128]  8: att_src2 [128]   9: att_dst2 [128]   10: b2 [128]
// Output: [64,128] f32

#define NN 50000
#define EE 1600000
#define TE (EE + NN)
#define C1 64
#define C2 128
#define NG 64
#define NB 196   // ceil(NN/256)

// ---- scratch ----
__device__ __align__(16) float g_xl1[NN * C1];
__device__ __align__(16) float g_as1[NN * 2];
__device__ __align__(16) float g_ad1[NN * 2];
__device__ __align__(16) float g_h1[NN * C1];
__device__ __align__(16) float g_xl2[NN * C2];
__device__ __align__(16) float g_as2[NN];
__device__ __align__(16) float g_ad2[NN];
__device__ __align__(16) float g_pool[NG * C2];
__device__ __align__(16) float g_cnt[NG];
__device__ int g_src[TE];
__device__ int g_dst[TE];
__device__ int g_batch[NN];
__device__ int g_deg[NN];
__device__ int g_rowstart[NN];
__device__ int g_cursor[NN];
__device__ int g_esrc[TE];
__device__ int g_bsum[256];
__device__ int g_boffs[256];
__device__ unsigned int g_odd_or;

// ============ zero: deg + pool + cnt + flag ============
__global__ void zero_kernel() {
    int i = blockIdx.x * 256 + threadIdx.x;
    if (i == 0) g_odd_or = 0u;
    if (i < NN) g_deg[i] = 0;
    if (i < NG * C2) g_pool[i] = 0.f;
    if (i < NG) g_cnt[i] = 0.f;
}

// ============ dtype detection (odd 32-bit words all zero <=> int64 LE) ============
__global__ void detect_kernel(const unsigned int* __restrict__ w) {
    unsigned int v = 0;
    long long stride = 2LL * (long long)gridDim.x * blockDim.x;
    for (long long j = 2LL * (blockIdx.x * blockDim.x + threadIdx.x) + 1;
         j < 2LL * EE; j += stride)
        v |= w[j];
#pragma unroll
    for (int o = 16; o; o >>= 1) v |= __shfl_down_sync(0xFFFFFFFFu, v, o);
    if ((threadIdx.x & 31) == 0 && v) atomicOr(&g_odd_or, v);
}

// ============ convert to int32 (+ self loops) + degree histogram ============
__global__ void convert_kernel(const void* __restrict__ ei, const void* __restrict__ batch) {
    int e = blockIdx.x * 256 + threadIdx.x;
    bool is64 = (g_odd_or == 0u);
    if (e < TE) {
        int s, d;
        if (e < EE) {
            if (is64) {
                s = (int)((const long long*)ei)[e];
                d = (int)((const long long*)ei)[EE + e];
            } else {
                s = ((const int*)ei)[e];
                d = ((const int*)ei)[EE + e];
            }
            s = min(max(s, 0), NN - 1);
            d = min(max(d, 0), NN - 1);
        } else { s = d = e - EE; }
        g_src[e] = s; g_dst[e] = d;
        atomicAdd(&g_deg[d], 1);
    }
    if (e < NN) {
        int g = is64 ? (int)((const long long*)batch)[e] : ((const int*)batch)[e];
        g_batch[e] = min(max(g, 0), NG - 1);
    }
}

// ============ 3-step exclusive scan over g_deg -> g_rowstart (+cursor copy) ============
__global__ void scan1_kernel() {
    __shared__ int sh[256];
    int b = blockIdx.x, t = threadIdx.x;
    int idx = b * 256 + t;
    sh[t] = (idx < NN) ? g_deg[idx] : 0;
    __syncthreads();
#pragma unroll
    for (int o = 128; o; o >>= 1) { if (t < o) sh[t] += sh[t + o]; __syncthreads(); }
    if (t == 0) g_bsum[b] = sh[0];
}
__global__ void scan2_kernel() {
    __shared__ int sh[256];
    int t = threadIdx.x;
    int own = (t < NB) ? g_bsum[t] : 0;
    sh[t] = own;
    __syncthreads();
#pragma unroll
    for (int o = 1; o < 256; o <<= 1) {
        int v = (t >= o) ? sh[t - o] : 0;
        __syncthreads();
        sh[t] += v;
        __syncthreads();
    }
    if (t < NB) g_boffs[t] = sh[t] - own;   // exclusive
}
__global__ void scan3_kernel() {
    __shared__ int sh[256];
    int b = blockIdx.x, t = threadIdx.x;
    int idx = b * 256 + t;
    int v = (idx < NN) ? g_deg[idx] : 0;
    sh[t] = v;
    __syncthreads();
#pragma unroll
    for (int o = 1; o < 256; o <<= 1) {
        int u = (t >= o) ? sh[t - o] : 0;
        __syncthreads();
        sh[t] += u;
        __syncthreads();
    }
    if (idx < NN) {
        int rs = g_boffs[b] + sh[t] - v;
        g_rowstart[idx] = rs;
        g_cursor[idx] = rs;
    }
}

// ============ scatter src ids into dst-grouped order ============
__global__ void scatter_kernel() {
    int e = blockIdx.x * 256 + threadIdx.x;
    if (e < TE) {
        int d = g_dst[e];
        int pos = atomicAdd(&g_cursor[d], 1);
        g_esrc[pos] = g_src[e];
    }
}

// ================= GEMM 1 + att1 epilogue (unchanged, proven) =================
__global__ void gemm1_kernel(const float* __restrict__ x, const float* __restrict__ W,
                             const float* __restrict__ atts, const float* __restrict__ attd) {
    __shared__ __align__(16) float Xs[32][68];
    __shared__ __align__(16) float Ws[32 * 64];
    int t = threadIdx.x;
    int n0 = blockIdx.x * 64;
    int node = t >> 2, q = t & 3;
    int tn = t >> 4, tc = t & 15;
    float acc[4][4] = {};
    const float4* W4 = (const float4*)W;

    for (int k0 = 0; k0 < 128; k0 += 32) {
        ((float4*)Ws)[t]       = W4[k0 * 16 + t];
        ((float4*)Ws)[t + 256] = W4[k0 * 16 + t + 256];
        int gn = n0 + node;
        const float4* xr = (const float4*)(x + (size_t)gn * 128 + k0);
#pragma unroll
        for (int i = 0; i < 2; i++) {
            int jj = 2 * q + i;
            float4 v = (gn < NN) ? xr[jj] : make_float4(0.f, 0.f, 0.f, 0.f);
            int k = 4 * jj;
            Xs[k][node] = v.x; Xs[k + 1][node] = v.y;
            Xs[k + 2][node] = v.z; Xs[k + 3][node] = v.w;
        }
        __syncthreads();
#pragma unroll
        for (int k = 0; k < 32; k++) {
            float4 b = *(const float4*)&Ws[k * 64 + 4 * tc];
            float4 a = *(const float4*)&Xs[k][4 * tn];
            acc[0][0] += a.x * b.x; acc[0][1] += a.x * b.y; acc[0][2] += a.x * b.z; acc[0][3] += a.x * b.w;
            acc[1][0] += a.y * b.x; acc[1][1] += a.y * b.y; acc[1][2] += a.y * b.z; acc[1][3] += a.y * b.w;
            acc[2][0] += a.z * b.x; acc[2][1] += a.z * b.y; acc[2][2] += a.z * b.z; acc[2][3] += a.z * b.w;
            acc[3][0] += a.w * b.x; acc[3][1] += a.w * b.y; acc[3][2] += a.w * b.z; acc[3][3] += a.w * b.w;
        }
        __syncthreads();
    }

    float4 asv = *(const float4*)(atts + 4 * tc);
    float4 adv = *(const float4*)(attd + 4 * tc);
#pragma unroll
    for (int i = 0; i < 4; i++) {
        int gn = n0 + 4 * tn + i;
        if (gn < NN)
            *(float4*)&g_xl1[(size_t)gn * 64 + 4 * tc] =
                make_float4(acc[i][0], acc[i][1], acc[i][2], acc[i][3]);
        float s = acc[i][0] * asv.x + acc[i][1] * asv.y + acc[i][2] * asv.z + acc[i][3] * asv.w;
        float d = acc[i][0] * adv.x + acc[i][1] * adv.y + acc[i][2] * adv.z + acc[i][3] * adv.w;
#pragma unroll
        for (int o = 4; o; o >>= 1) {
            s += __shfl_down_sync(0xFFFFFFFFu, s, o, 8);
            d += __shfl_down_sync(0xFFFFFFFFu, d, o, 8);
        }
        if (gn < NN) {
            if (tc == 0) { g_as1[2 * gn]     = s; g_ad1[2 * gn]     = d; }
            if (tc == 8) { g_as1[2 * gn + 1] = s; g_ad1[2 * gn + 1] = d; }
        }
    }
}

// ========== edge1 CSR: warp per dst node, gather-only, fused norm+b1+ELU -> h1 ==========
// lane l: feats 2l,2l+1 (lanes 0-15 head0, 16-31 head1). No atomics.
__global__ void edge1_kernel(const float* __restrict__ b1) {
    int w = (blockIdx.x * 256 + threadIdx.x) >> 5;
    int l = threadIdx.x & 31;
    if (w >= NN) return;
    int start = g_rowstart[w], deg = g_deg[w];
    float2 ad = *(const float2*)&g_ad1[2 * w];
    float accx = 0.f, accy = 0.f, den0 = 0.f, den1 = 0.f;
#pragma unroll 4
    for (int j = start; j < start + deg; j++) {
        int s = g_esrc[j];                       // warp-broadcast load
        float2 as = *(const float2*)&g_as1[2 * s];
        float e0 = as.x + ad.x; e0 = e0 > 0.f ? e0 : 0.2f * e0;
        float e1 = as.y + ad.y; e1 = e1 > 0.f ? e1 : 0.2f * e1;
        float ex0 = __expf(e0), ex1 = __expf(e1);
        den0 += ex0; den1 += ex1;
        float2 v = ((const float2*)(g_xl1 + (size_t)s * 64))[l];
        float ex = (l < 16) ? ex0 : ex1;
        accx += ex * v.x; accy += ex * v.y;
    }
    float rd = 1.f / ((l < 16) ? den0 : den1);
    float2 bb = *(const float2*)(b1 + 2 * l);
    float vx = accx * rd + bb.x; vx = vx > 0.f ? vx : (__expf(vx) - 1.f);
    float vy = accy * rd + bb.y; vy = vy > 0.f ? vy : (__expf(vy) - 1.f);
    ((float2*)(g_h1 + (size_t)w * 64))[l] = make_float2(vx, vy);
}

// ================= GEMM 2 (plain h1 input) + att2 epilogue =================
__global__ void gemm2_kernel(const float* __restrict__ W,
                             const float* __restrict__ atts, const float* __restrict__ attd) {
    __shared__ __align__(16) float Xs[32][68];
    __shared__ __align__(16) float Ws[32 * 128];
    int t = threadIdx.x;
    int n0 = blockIdx.x * 64;
    int node = t >> 2, q = t & 3;
    int tn = t >> 4, tc = t & 15;
    float acc[4][8] = {};

    for (int k0 = 0; k0 < 64; k0 += 32) {
        const float4* W4 = (const float4*)(W + k0 * 128);
#pragma unroll
        for (int i = 0; i < 4; i++)
            ((float4*)Ws)[t + 256 * i] = W4[t + 256 * i];
        int gn = n0 + node;
        const float4* hr = (const float4*)(g_h1 + (size_t)gn * 64 + k0);
#pragma unroll
        for (int i = 0; i < 2; i++) {
            int jj = 2 * q + i;
            float4 v = (gn < NN) ? hr[jj] : make_float4(0.f, 0.f, 0.f, 0.f);
            int k = 4 * jj;
            Xs[k][node] = v.x; Xs[k + 1][node] = v.y;
            Xs[k + 2][node] = v.z; Xs[k + 3][node] = v.w;
        }
        __syncthreads();
#pragma unroll
        for (int k = 0; k < 32; k++) {
            float4 a   = *(const float4*)&Xs[k][4 * tn];
            float4 b0  = *(const float4*)&Ws[k * 128 + 8 * tc];
            float4 b1v = *(const float4*)&Ws[k * 128 + 8 * tc + 4];
#pragma unroll
            for (int i = 0; i < 4; i++) {
                float ai = (i == 0) ? a.x : (i == 1) ? a.y : (i == 2) ? a.z : a.w;
                acc[i][0] += ai * b0.x;  acc[i][1] += ai * b0.y;
                acc[i][2] += ai * b0.z;  acc[i][3] += ai * b0.w;
                acc[i][4] += ai * b1v.x; acc[i][5] += ai * b1v.y;
                acc[i][6] += ai * b1v.z; acc[i][7] += ai * b1v.w;
            }
        }
        __syncthreads();
    }

    float4 as0 = *(const float4*)(atts + 8 * tc), asv1 = *(const float4*)(atts + 8 * tc + 4);
    float4 ad0 = *(const float4*)(attd + 8 * tc), adv1 = *(const float4*)(attd + 8 * tc + 4);
#pragma unroll
    for (int i = 0; i < 4; i++) {
        int gn = n0 + 4 * tn + i;
        if (gn < NN) {
            float4* xr = (float4*)(g_xl2 + (size_t)gn * 128 + 8 * tc);
            xr[0] = make_float4(acc[i][0], acc[i][1], acc[i][2], acc[i][3]);
            xr[1] = make_float4(acc[i][4], acc[i][5], acc[i][6], acc[i][7]);
        }
        float s = acc[i][0] * as0.x + acc[i][1] * as0.y + acc[i][2] * as0.z + acc[i][3] * as0.w
                + acc[i][4] * asv1.x + acc[i][5] * asv1.y + acc[i][6] * asv1.z + acc[i][7] * asv1.w;
        float d = acc[i][0] * ad0.x + acc[i][1] * ad0.y + acc[i][2] * ad0.z + acc[i][3] * ad0.w
                + acc[i][4] * adv1.x + acc[i][5] * adv1.y + acc[i][6] * adv1.z + acc[i][7] * adv1.w;
#pragma unroll
        for (int o = 8; o; o >>= 1) {
            s += __shfl_down_sync(0xFFFFFFFFu, s, o, 16);
            d += __shfl_down_sync(0xFFFFFFFFu, d, o, 16);
        }
        if (gn < NN && tc == 0) { g_as2[gn] = s; g_ad2[gn] = d; }
    }
}

// ========== edge2 CSR: warp per dst node, fused norm+b2+ELU + pool RED ==========
// lane l: float4 feats 4l..4l+3. Output goes straight into pool accumulators.
__global__ void edge2_kernel(const float* __restrict__ b2) {
    int w = (blockIdx.x * 256 + threadIdx.x) >> 5;
    int l = threadIdx.x & 31;
    if (w >= NN) return;
    int start = g_rowstart[w], deg = g_deg[w];
    float ad = g_ad2[w];
    float ax = 0.f, ay = 0.f, az = 0.f, aw = 0.f, den = 0.f;
#pragma unroll 4
    for (int j = start; j < start + deg; j++) {
        int s = g_esrc[j];                       // warp-broadcast load
        float ev = g_as2[s] + ad;
        ev = ev > 0.f ? ev : 0.2f * ev;
        float ex = __expf(ev);
        den += ex;
        float4 v = ((const float4*)(g_xl2 + (size_t)s * 128))[l];
        ax += ex * v.x; ay += ex * v.y; az += ex * v.z; aw += ex * v.w;
    }
    float rd = 1.f / den;
    float4 bb = *(const float4*)(b2 + 4 * l);
    ax = ax * rd + bb.x; ax = ax > 0.f ? ax : (__expf(ax) - 1.f);
    ay = ay * rd + bb.y; ay = ay > 0.f ? ay : (__expf(ay) - 1.f);
    az = az * rd + bb.z; az = az > 0.f ? az : (__expf(az) - 1.f);
    aw = aw * rd + bb.w; aw = aw > 0.f ? aw : (__expf(aw) - 1.f);
    int g = g_batch[w];
    atomicAdd((float4*)&g_pool[g * 128 + 4 * l], make_float4(ax, ay, az, aw));
    if (l == 0) atomicAdd(&g_cnt[g], 1.f);
}

__global__ void final_kernel(float* __restrict__ out) {
    int g = blockIdx.x, c = threadIdx.x;
    out[g * 128 + c] = g_pool[g * 128 + c] / fmaxf(g_cnt[g], 1.f);
}

// ============================ launch ============================
extern "C" void kernel_launch(void* const* d_in, const int* in_sizes, int n_in,
                              void* d_out, int out_size) {
    const float* x   = (const float*)d_in[0];
    const void*  ei  = d_in[1];
    const void*  bat = d_in[2];
    const float* W1  = (const float*)d_in[3];
    const float* as1 = (const float*)d_in[4];
    const float* ad1 = (const float*)d_in[5];
    const float* b1  = (const float*)d_in[6];
    const float* W2  = (const float*)d_in[7];
    const float* as2 = (const float*)d_in[8];
    const float* ad2 = (const float*)d_in[9];
    const float* b2  = (const float*)d_in[10];
    float* out = (float*)d_out;

    zero_kernel<<<(NG * C2 + 255) / 256, 256>>>();   // covers NN via? no:
    // NN > NG*C2; use NN-sized grid:
    // (kept single launch below)
    zero_kernel<<<(NN + 255) / 256, 256>>>();

    detect_kernel<<<512, 256>>>((const unsigned int*)ei);
    convert_kernel<<<(TE + 255) / 256, 256>>>(ei, bat);
    scan1_kernel<<<NB, 256>>>();
    scan2_kernel<<<1, 256>>>();
    scan3_kernel<<<NB, 256>>>();
    scatter_kernel<<<(TE + 255) / 256, 256>>>();

    gemm1_kernel<<<(NN + 63) / 64, 256>>>(x, W1, as1, ad1);
    edge1_kernel<<<(NN * 32 + 255) / 256, 256>>>(b1);
    gemm2_kernel<<<(NN + 63) / 64, 256>>>(W2, as2, ad2);
    edge2_kernel<<<(NN * 32 + 255) / 256, 256>>>(b2);
    final_kernel<<<NG, 128>>>(out);
}